// round 1
// baseline (speedup 1.0000x reference)
#include <cuda_runtime.h>
#include <cuda_bf16.h>
#include <math.h>

// Problem constants
#define BB 2
#define SS 2048
#define DD 2048
#define HH 16
#define DK 128
#define MM (BB*SS)          // 4096
#define KEY_SCALE 0.08838834764831843f  // 1/sqrt(128)

// -------------------- scratch (device globals; no allocations) --------------------
__device__ float g_q[(size_t)BB*HH*SS*DK];   // [b,h,s,dk]
__device__ float g_k[(size_t)BB*HH*SS*DK];
__device__ float g_v[(size_t)BB*HH*SS*DK];
__device__ float g_gate[(size_t)BB*SS*HH];   // [b,s,h]
__device__ float g_o[(size_t)BB*SS*DD];      // [b,s,h*dk]

// ==================== SGEMM: C[M,N] = X[M,K] * W[N,K]^T + bias ====================
// mode 0: out row-major [M,N]
// mode 1: out scattered to [b,h,s,dk] layout (n = h*DK+dk, m = b*S+s)
#define GBM 128
#define GBN 128
#define GBK 16

__global__ __launch_bounds__(256) void gemm_xwt(const float* __restrict__ X,
                                                const float* __restrict__ W,
                                                const float* __restrict__ bias,
                                                float* __restrict__ out,
                                                int mode) {
    __shared__ float Xs[GBK][GBM];
    __shared__ float Ws[GBK][GBN];

    const int m0 = blockIdx.y * GBM;
    const int n0 = blockIdx.x * GBN;
    const int tid = threadIdx.x;
    const int tx = tid & 15;      // 0..15
    const int ty = tid >> 4;      // 0..15

    const int lr = tid >> 2;           // 0..63 (load row)
    const int lc = (tid & 3) * 4;      // 0,4,8,12 (load k-col base)

    float acc[8][8];
#pragma unroll
    for (int i = 0; i < 8; ++i)
#pragma unroll
        for (int j = 0; j < 8; ++j) acc[i][j] = 0.f;

    for (int k0 = 0; k0 < DD; k0 += GBK) {
#pragma unroll
        for (int half = 0; half < 2; ++half) {
            const int row = lr + half * 64;
            float4 xv = *(const float4*)&X[(size_t)(m0 + row) * DD + k0 + lc];
            Xs[lc + 0][row] = xv.x; Xs[lc + 1][row] = xv.y;
            Xs[lc + 2][row] = xv.z; Xs[lc + 3][row] = xv.w;
            float4 wv = *(const float4*)&W[(size_t)(n0 + row) * DD + k0 + lc];
            Ws[lc + 0][row] = wv.x; Ws[lc + 1][row] = wv.y;
            Ws[lc + 2][row] = wv.z; Ws[lc + 3][row] = wv.w;
        }
        __syncthreads();

#pragma unroll
        for (int k = 0; k < GBK; ++k) {
            float a[8], b[8];
            *(float4*)&a[0] = *(const float4*)&Xs[k][ty * 8];
            *(float4*)&a[4] = *(const float4*)&Xs[k][ty * 8 + 4];
            *(float4*)&b[0] = *(const float4*)&Ws[k][tx * 8];
            *(float4*)&b[4] = *(const float4*)&Ws[k][tx * 8 + 4];
#pragma unroll
            for (int i = 0; i < 8; ++i)
#pragma unroll
                for (int j = 0; j < 8; ++j) acc[i][j] += a[i] * b[j];
        }
        __syncthreads();
    }

#pragma unroll
    for (int i = 0; i < 8; ++i) {
        const int m = m0 + ty * 8 + i;
#pragma unroll
        for (int j = 0; j < 8; ++j) {
            const int n = n0 + tx * 8 + j;
            const float c = acc[i][j] + bias[n];
            if (mode == 0) {
                out[(size_t)m * DD + n] = c;
            } else {
                const int b_ = m >> 11, s_ = m & (SS - 1);
                const int h_ = n >> 7, dk_ = n & (DK - 1);
                out[(((size_t)(b_ * HH + h_) * SS) + s_) * DK + dk_] = c;
            }
        }
    }
}

// ==================== gate: g[b,s,h] = sigmoid(states[m,:] . Wg[h,:] + bg[h]) ====================
__global__ __launch_bounds__(128) void gate_kernel(const float* __restrict__ X,
                                                   const float* __restrict__ Wg,
                                                   const float* __restrict__ bg,
                                                   float* __restrict__ gate) {
    __shared__ float xs[DD];
    const int m = blockIdx.x;
    for (int i = threadIdx.x * 4; i < DD; i += 128 * 4)
        *(float4*)&xs[i] = *(const float4*)&X[(size_t)m * DD + i];
    __syncthreads();

    const int w = threadIdx.x >> 5, lane = threadIdx.x & 31;
    for (int h = w; h < HH; h += 4) {
        const float* wg = &Wg[(size_t)h * DD];
        float sum = 0.f;
        for (int k = lane; k < DD; k += 32) sum += xs[k] * wg[k];
#pragma unroll
        for (int off = 16; off; off >>= 1) sum += __shfl_xor_sync(0xffffffffu, sum, off);
        if (lane == 0) {
            const float z = sum + bg[h];
            gate[(size_t)m * HH + h] = 1.f / (1.f + __expf(-z));
        }
    }
}

// ==================== flash attention (causal, ALiBi, fp32) ====================
// grid (S/64, H, B), 256 threads. smem: Qt[128][64] Kt[128][64] Vs[64][128] Ss[64][65] + m/l/alpha
#define BQ 64
#define BKT 64
#define SS_LD 65
#define ATTN_SMEM_FLOATS (128*64 + 128*64 + 64*128 + 64*SS_LD + 3*64)
#define ATTN_SMEM_BYTES (ATTN_SMEM_FLOATS * 4)

__global__ __launch_bounds__(256, 1) void attn_kernel(const float* __restrict__ q,
                                                      const float* __restrict__ k,
                                                      const float* __restrict__ v,
                                                      const float* __restrict__ gate,
                                                      float* __restrict__ o,
                                                      const float* __restrict__ head_scale) {
    extern __shared__ float sm[];
    float* Qt  = sm;                 // [dk][r] transposed
    float* Kt  = Qt + 128 * 64;
    float* Vs  = Kt + 128 * 64;      // [r][dk]
    float* Sst = Vs + 64 * 128;      // [r][c] stride 65
    float* m_s = Sst + 64 * SS_LD;
    float* l_s = m_s + 64;
    float* a_s = l_s + 64;

    const int qt = blockIdx.x;
    const int h  = blockIdx.y;
    const int b  = blockIdx.z;
    const int tid = threadIdx.x;
    const float hs = head_scale[h];

    const size_t bh = ((size_t)b * HH + h) * SS;   // row base into [b,h,s,*]

    // load Q tile, transposed
    {
        const int r = tid >> 2;
        const int cq = (tid & 3) * 32;
        const float* src = q + (bh + (size_t)qt * BQ + r) * DK + cq;
#pragma unroll
        for (int j = 0; j < 8; ++j) {
            float4 xv = *(const float4*)(src + 4 * j);
            const int dk = cq + 4 * j;
            Qt[(dk + 0) * 64 + r] = xv.x; Qt[(dk + 1) * 64 + r] = xv.y;
            Qt[(dk + 2) * 64 + r] = xv.z; Qt[(dk + 3) * 64 + r] = xv.w;
        }
    }
    if (tid < 64) { m_s[tid] = -INFINITY; l_s[tid] = 0.f; }

    float acc[4][8];
#pragma unroll
    for (int i = 0; i < 4; ++i)
#pragma unroll
        for (int j = 0; j < 8; ++j) acc[i][j] = 0.f;

    const int ty = tid >> 4, tx = tid & 15;
    const int r0 = ty * 4;

    for (int kt = 0; kt <= qt; ++kt) {
        __syncthreads();  // protect Kt/Vs/Ss against previous iter readers (also fences Q/m/l init)

        // load K (transposed) and V (row-major)
        {
            const int r = tid >> 2;
            const int cq = (tid & 3) * 32;
            const float* ksrc = k + (bh + (size_t)kt * BKT + r) * DK + cq;
            const float* vsrc = v + (bh + (size_t)kt * BKT + r) * DK + cq;
#pragma unroll
            for (int j = 0; j < 8; ++j) {
                float4 kv = *(const float4*)(ksrc + 4 * j);
                const int dk = cq + 4 * j;
                Kt[(dk + 0) * 64 + r] = kv.x; Kt[(dk + 1) * 64 + r] = kv.y;
                Kt[(dk + 2) * 64 + r] = kv.z; Kt[(dk + 3) * 64 + r] = kv.w;
                *(float4*)&Vs[r * 128 + cq + 4 * j] = *(const float4*)(vsrc + 4 * j);
            }
        }
        __syncthreads();

        // ---- stage 1: S = Q K^T (4x4 per thread) ----
        {
            const int c0 = tx * 4;
            float sv[4][4];
#pragma unroll
            for (int i = 0; i < 4; ++i)
#pragma unroll
                for (int j = 0; j < 4; ++j) sv[i][j] = 0.f;

#pragma unroll 4
            for (int kk = 0; kk < 128; ++kk) {
                float a[4], bv[4];
                *(float4*)a  = *(const float4*)&Qt[kk * 64 + r0];
                *(float4*)bv = *(const float4*)&Kt[kk * 64 + c0];
#pragma unroll
                for (int i = 0; i < 4; ++i)
#pragma unroll
                    for (int j = 0; j < 4; ++j) sv[i][j] += a[i] * bv[j];
            }
#pragma unroll
            for (int i = 0; i < 4; ++i) {
                const int qi = qt * BQ + r0 + i;
#pragma unroll
                for (int j = 0; j < 4; ++j) {
                    const int kj = kt * BKT + c0 + j;
                    float val = (kj <= qi) ? (sv[i][j] * KEY_SCALE + (float)(kj - qi) * hs)
                                           : -INFINITY;
                    Sst[(r0 + i) * SS_LD + c0 + j] = val;
                }
            }
        }
        __syncthreads();

        // ---- stage 2: online softmax row update (4 threads per row) ----
        {
            const int row = tid >> 2;
            const int quarter = tid & 3;
            float* srow = &Sst[row * SS_LD];
            const int cbase = quarter * 16;
            float mx = -INFINITY;
#pragma unroll
            for (int c = 0; c < 16; ++c) mx = fmaxf(mx, srow[cbase + c]);
            mx = fmaxf(mx, __shfl_xor_sync(0xffffffffu, mx, 1));
            mx = fmaxf(mx, __shfl_xor_sync(0xffffffffu, mx, 2));
            const float m_old = m_s[row];
            const float m_new = fmaxf(m_old, mx);
            float psum = 0.f;
#pragma unroll
            for (int c = 0; c < 16; ++c) {
                const float p = __expf(srow[cbase + c] - m_new);
                srow[cbase + c] = p;
                psum += p;
            }
            psum += __shfl_xor_sync(0xffffffffu, psum, 1);
            psum += __shfl_xor_sync(0xffffffffu, psum, 2);
            if (quarter == 0) {
                const float alpha = __expf(m_old - m_new);
                a_s[row] = alpha;
                l_s[row] = l_s[row] * alpha + psum;
                m_s[row] = m_new;
            }
        }
        __syncthreads();

        // ---- stage 3: O = alpha*O + P V ----
        {
            const int c0 = tx * 8;
            float al[4];
#pragma unroll
            for (int i = 0; i < 4; ++i) al[i] = a_s[r0 + i];
#pragma unroll
            for (int i = 0; i < 4; ++i)
#pragma unroll
                for (int j = 0; j < 8; ++j) acc[i][j] *= al[i];

#pragma unroll 4
            for (int kk = 0; kk < 64; ++kk) {
                float p[4];
#pragma unroll
                for (int i = 0; i < 4; ++i) p[i] = Sst[(r0 + i) * SS_LD + kk];
                float vv[8];
                *(float4*)&vv[0] = *(const float4*)&Vs[kk * 128 + c0];
                *(float4*)&vv[4] = *(const float4*)&Vs[kk * 128 + c0 + 4];
#pragma unroll
                for (int i = 0; i < 4; ++i)
#pragma unroll
                    for (int j = 0; j < 8; ++j) acc[i][j] += p[i] * vv[j];
            }
        }
    }

    // epilogue: normalize, gate, store to [b,s,h,dk]
    {
        const int c0 = tx * 8;
#pragma unroll
        for (int i = 0; i < 4; ++i) {
            const int qg = qt * BQ + r0 + i;
            const float inv = 1.f / l_s[r0 + i];
            const float gt = gate[((size_t)b * SS + qg) * HH + h];
            const float sc = inv * gt;
            float4 o0, o1;
            o0.x = acc[i][0] * sc; o0.y = acc[i][1] * sc;
            o0.z = acc[i][2] * sc; o0.w = acc[i][3] * sc;
            o1.x = acc[i][4] * sc; o1.y = acc[i][5] * sc;
            o1.z = acc[i][6] * sc; o1.w = acc[i][7] * sc;
            float* dst = o + (((size_t)b * SS + qg) * HH + h) * DK + c0;
            *(float4*)dst = o0;
            *(float4*)(dst + 4) = o1;
        }
    }
}

// ==================== launcher ====================
extern "C" void kernel_launch(void* const* d_in, const int* in_sizes, int n_in,
                              void* d_out, int out_size) {
    const float* states     = (const float*)d_in[0];
    // d_in[1] = bias_mask (unused: computed analytically, exact match)
    const float* head_scale = (const float*)d_in[2];
    const float* Wq = (const float*)d_in[3];
    const float* bq = (const float*)d_in[4];
    const float* Wk = (const float*)d_in[5];
    const float* bk = (const float*)d_in[6];
    const float* Wv = (const float*)d_in[7];
    const float* bv = (const float*)d_in[8];
    const float* Wg = (const float*)d_in[9];
    const float* bg = (const float*)d_in[10];
    const float* Wo = (const float*)d_in[11];
    const float* bo = (const float*)d_in[12];

    float *qb, *kb, *vb, *gb, *ob;
    cudaGetSymbolAddress((void**)&qb, g_q);
    cudaGetSymbolAddress((void**)&kb, g_k);
    cudaGetSymbolAddress((void**)&vb, g_v);
    cudaGetSymbolAddress((void**)&gb, g_gate);
    cudaGetSymbolAddress((void**)&ob, g_o);

    cudaFuncSetAttribute(attn_kernel, cudaFuncAttributeMaxDynamicSharedMemorySize,
                         ATTN_SMEM_BYTES);

    dim3 gemm_grid(DD / GBN, MM / GBM);   // (16, 32)
    gemm_xwt<<<gemm_grid, 256>>>(states, Wq, bq, qb, 1);
    gemm_xwt<<<gemm_grid, 256>>>(states, Wk, bk, kb, 1);
    gemm_xwt<<<gemm_grid, 256>>>(states, Wv, bv, vb, 1);
    gate_kernel<<<MM, 128>>>(states, Wg, bg, gb);

    dim3 attn_grid(SS / BQ, HH, BB);      // (32, 16, 2)
    attn_kernel<<<attn_grid, 256, ATTN_SMEM_BYTES>>>(qb, kb, vb, gb, ob, head_scale);

    gemm_xwt<<<gemm_grid, 256>>>(ob, Wo, bo, (float*)d_out, 0);
}

// round 2
// speedup vs baseline: 1.7773x; 1.7773x over previous
#include <cuda_runtime.h>
#include <cuda_bf16.h>
#include <math.h>
#include <stdint.h>

// Problem constants
#define BB 2
#define SS 2048
#define DD 2048
#define HH 16
#define DK 128
#define MM (BB*SS)          // 4096
#define KEY_SCALE 0.08838834764831843f  // 1/sqrt(128)

// -------------------- scratch (device globals; no allocations) --------------------
__device__ float g_q[(size_t)BB*HH*SS*DK];   // [b,h,s,dk]
__device__ float g_k[(size_t)BB*HH*SS*DK];
__device__ float g_v[(size_t)BB*HH*SS*DK];
__device__ float g_gate[(size_t)BB*SS*HH];   // [b,s,h]
__device__ float g_o[(size_t)BB*SS*DD];      // [b,s,h*dk]

// ==================== TF32 tensor-core GEMM ====================
// C[M,N] = X[M,K] * W[N,K]^T + bias      (K = DD = 2048)
// mode 0: out row-major [M,N]
// mode 1: out scattered to [b,h,s,dk] (n = h*DK+dk, m = b*SS+s)
#define TBM 128
#define TBN 128
#define TBK 16
#define TLD 20                  // row stride in floats (16 + 4 pad)
#define KTILES (DD / TBK)       // 128

__device__ __forceinline__ float tf32r(float x) {
    uint32_t u;
    asm("cvt.rna.tf32.f32 %0, %1;" : "=r"(u) : "f"(x));
    return __uint_as_float(u);
}

__device__ __forceinline__ void mma_tf32(float* d, const uint32_t* a, const uint32_t* b) {
    asm volatile(
        "mma.sync.aligned.m16n8k8.row.col.f32.tf32.tf32.f32 "
        "{%0,%1,%2,%3}, {%4,%5,%6,%7}, {%8,%9}, {%0,%1,%2,%3};"
        : "+f"(d[0]), "+f"(d[1]), "+f"(d[2]), "+f"(d[3])
        : "r"(a[0]), "r"(a[1]), "r"(a[2]), "r"(a[3]), "r"(b[0]), "r"(b[1]));
}

__global__ __launch_bounds__(256) void gemm_tf32(const float* __restrict__ X,
                                                 const float* __restrict__ W,
                                                 const float* __restrict__ bias,
                                                 float* __restrict__ out,
                                                 int mode) {
    __shared__ float As[3][TBM * TLD];
    __shared__ float Bs[3][TBN * TLD];

    const int tid  = threadIdx.x;
    const int lane = tid & 31;
    const int warp = tid >> 5;
    const int gid  = lane >> 2;      // 0..7
    const int ctid = lane & 3;       // 0..3
    const int wr   = warp >> 2;      // 0..1
    const int wc   = warp & 3;       // 0..3
    const int mw   = wr * 64;        // warp m-offset in tile
    const int nw   = wc * 32;        // warp n-offset in tile

    const int m0 = blockIdx.y * TBM;
    const int n0 = blockIdx.x * TBN;

    // global load mapping: each thread loads 2 float4 per operand tile
    const int lrow = tid >> 2;            // 0..63
    const int lcol = (tid & 3) * 4;       // 0,4,8,12

    const float* Xp0 = X + (size_t)(m0 + lrow) * DD + lcol;
    const float* Xp1 = X + (size_t)(m0 + lrow + 64) * DD + lcol;
    const float* Wp0 = W + (size_t)(n0 + lrow) * DD + lcol;
    const float* Wp1 = W + (size_t)(n0 + lrow + 64) * DD + lcol;

    float4 sx0, sx1, sw0, sw1;   // staging registers

#define LDG_TILE(t) do {                                        \
        const size_t off = (size_t)(t) * TBK;                   \
        sx0 = *(const float4*)(Xp0 + off);                      \
        sx1 = *(const float4*)(Xp1 + off);                      \
        sw0 = *(const float4*)(Wp0 + off);                      \
        sw1 = *(const float4*)(Wp1 + off);                      \
    } while (0)

#define STS_TILE(buf) do {                                      \
        float* ap0 = &As[buf][lrow * TLD + lcol];               \
        ap0[0] = tf32r(sx0.x); ap0[1] = tf32r(sx0.y);           \
        ap0[2] = tf32r(sx0.z); ap0[3] = tf32r(sx0.w);           \
        float* ap1 = &As[buf][(lrow + 64) * TLD + lcol];        \
        ap1[0] = tf32r(sx1.x); ap1[1] = tf32r(sx1.y);           \
        ap1[2] = tf32r(sx1.z); ap1[3] = tf32r(sx1.w);           \
        float* bp0 = &Bs[buf][lrow * TLD + lcol];               \
        bp0[0] = tf32r(sw0.x); bp0[1] = tf32r(sw0.y);           \
        bp0[2] = tf32r(sw0.z); bp0[3] = tf32r(sw0.w);           \
        float* bp1 = &Bs[buf][(lrow + 64) * TLD + lcol];        \
        bp1[0] = tf32r(sw1.x); bp1[1] = tf32r(sw1.y);           \
        bp1[2] = tf32r(sw1.z); bp1[3] = tf32r(sw1.w);           \
    } while (0)

    float acc[4][4][4];
#pragma unroll
    for (int i = 0; i < 4; ++i)
#pragma unroll
        for (int j = 0; j < 4; ++j)
#pragma unroll
            for (int r = 0; r < 4; ++r) acc[i][j][r] = 0.f;

    // prologue: tile 0 -> buf 0, prefetch tile 1 into regs
    LDG_TILE(0);
    STS_TILE(0);
    LDG_TILE(1);

    for (int t = 0; t < KTILES; ++t) {
        const int bufc = t % 3;
        if (t + 1 < KTILES) {
            STS_TILE((t + 1) % 3);
        }
        if (t + 2 < KTILES) {
            LDG_TILE(t + 2);
        }
        __syncthreads();

        const float* Ab = As[bufc];
        const float* Bb = Bs[bufc];

#pragma unroll
        for (int ks = 0; ks < 2; ++ks) {
            const int kk = ks * 8;
            uint32_t a[4][4], b[4][2];
#pragma unroll
            for (int mt = 0; mt < 4; ++mt) {
                const int r = mw + mt * 16 + gid;
                a[mt][0] = __float_as_uint(Ab[(r)     * TLD + kk + ctid]);
                a[mt][1] = __float_as_uint(Ab[(r + 8) * TLD + kk + ctid]);
                a[mt][2] = __float_as_uint(Ab[(r)     * TLD + kk + ctid + 4]);
                a[mt][3] = __float_as_uint(Ab[(r + 8) * TLD + kk + ctid + 4]);
            }
#pragma unroll
            for (int nt = 0; nt < 4; ++nt) {
                const int c = nw + nt * 8 + gid;
                b[nt][0] = __float_as_uint(Bb[c * TLD + kk + ctid]);
                b[nt][1] = __float_as_uint(Bb[c * TLD + kk + ctid + 4]);
            }
#pragma unroll
            for (int mt = 0; mt < 4; ++mt)
#pragma unroll
                for (int nt = 0; nt < 4; ++nt)
                    mma_tf32(acc[mt][nt], a[mt], b[nt]);
        }
    }

    // epilogue
#pragma unroll
    for (int mt = 0; mt < 4; ++mt) {
#pragma unroll
        for (int nt = 0; nt < 4; ++nt) {
            const int row0 = m0 + mw + mt * 16 + gid;
            const int col  = n0 + nw + nt * 8 + ctid * 2;
            const float b0 = bias[col], b1 = bias[col + 1];
            float2 v0 = make_float2(acc[mt][nt][0] + b0, acc[mt][nt][1] + b1);
            float2 v1 = make_float2(acc[mt][nt][2] + b0, acc[mt][nt][3] + b1);
            if (mode == 0) {
                *(float2*)&out[(size_t)row0 * DD + col] = v0;
                *(float2*)&out[(size_t)(row0 + 8) * DD + col] = v1;
            } else {
                const int h_ = col >> 7, dk_ = col & (DK - 1);
                const int b0_ = row0 >> 11, s0_ = row0 & (SS - 1);
                const int s1_ = (row0 + 8) & (SS - 1);
                *(float2*)&out[(((size_t)(b0_ * HH + h_) * SS) + s0_) * DK + dk_] = v0;
                *(float2*)&out[(((size_t)(b0_ * HH + h_) * SS) + s1_) * DK + dk_] = v1;
            }
        }
    }
#undef LDG_TILE
#undef STS_TILE
}

// ==================== gate: g[b,s,h] = sigmoid(states[m,:] . Wg[h,:] + bg[h]) ====================
__global__ __launch_bounds__(128) void gate_kernel(const float* __restrict__ X,
                                                   const float* __restrict__ Wg,
                                                   const float* __restrict__ bg,
                                                   float* __restrict__ gate) {
    __shared__ float xs[DD];
    const int m = blockIdx.x;
    for (int i = threadIdx.x * 4; i < DD; i += 128 * 4)
        *(float4*)&xs[i] = *(const float4*)&X[(size_t)m * DD + i];
    __syncthreads();

    const int w = threadIdx.x >> 5, lane = threadIdx.x & 31;
    for (int h = w; h < HH; h += 4) {
        const float* wg = &Wg[(size_t)h * DD];
        float sum = 0.f;
        for (int k = lane; k < DD; k += 32) sum += xs[k] * wg[k];
#pragma unroll
        for (int off = 16; off; off >>= 1) sum += __shfl_xor_sync(0xffffffffu, sum, off);
        if (lane == 0) {
            const float z = sum + bg[h];
            gate[(size_t)m * HH + h] = 1.f / (1.f + __expf(-z));
        }
    }
}

// ==================== flash attention (causal, ALiBi, fp32) ====================
#define BQ 64
#define BKT 64
#define SS_LD 65
#define ATTN_SMEM_FLOATS (128*64 + 128*64 + 64*128 + 64*SS_LD + 3*64)
#define ATTN_SMEM_BYTES (ATTN_SMEM_FLOATS * 4)

__global__ __launch_bounds__(256, 1) void attn_kernel(const float* __restrict__ q,
                                                      const float* __restrict__ k,
                                                      const float* __restrict__ v,
                                                      const float* __restrict__ gate,
                                                      float* __restrict__ o,
                                                      const float* __restrict__ head_scale) {
    extern __shared__ float sm[];
    float* Qt  = sm;                 // [dk][r] transposed
    float* Kt  = Qt + 128 * 64;
    float* Vs  = Kt + 128 * 64;      // [r][dk]
    float* Sst = Vs + 64 * 128;      // [r][c] stride 65
    float* m_s = Sst + 64 * SS_LD;
    float* l_s = m_s + 64;
    float* a_s = l_s + 64;

    const int qt = blockIdx.x;
    const int h  = blockIdx.y;
    const int b  = blockIdx.z;
    const int tid = threadIdx.x;
    const float hs = head_scale[h];

    const size_t bh = ((size_t)b * HH + h) * SS;

    {
        const int r = tid >> 2;
        const int cq = (tid & 3) * 32;
        const float* src = q + (bh + (size_t)qt * BQ + r) * DK + cq;
#pragma unroll
        for (int j = 0; j < 8; ++j) {
            float4 xv = *(const float4*)(src + 4 * j);
            const int dk = cq + 4 * j;
            Qt[(dk + 0) * 64 + r] = xv.x; Qt[(dk + 1) * 64 + r] = xv.y;
            Qt[(dk + 2) * 64 + r] = xv.z; Qt[(dk + 3) * 64 + r] = xv.w;
        }
    }
    if (tid < 64) { m_s[tid] = -INFINITY; l_s[tid] = 0.f; }

    float acc[4][8];
#pragma unroll
    for (int i = 0; i < 4; ++i)
#pragma unroll
        for (int j = 0; j < 8; ++j) acc[i][j] = 0.f;

    const int ty = tid >> 4, tx = tid & 15;
    const int r0 = ty * 4;

    for (int kt = 0; kt <= qt; ++kt) {
        __syncthreads();

        {
            const int r = tid >> 2;
            const int cq = (tid & 3) * 32;
            const float* ksrc = k + (bh + (size_t)kt * BKT + r) * DK + cq;
            const float* vsrc = v + (bh + (size_t)kt * BKT + r) * DK + cq;
#pragma unroll
            for (int j = 0; j < 8; ++j) {
                float4 kv = *(const float4*)(ksrc + 4 * j);
                const int dk = cq + 4 * j;
                Kt[(dk + 0) * 64 + r] = kv.x; Kt[(dk + 1) * 64 + r] = kv.y;
                Kt[(dk + 2) * 64 + r] = kv.z; Kt[(dk + 3) * 64 + r] = kv.w;
                *(float4*)&Vs[r * 128 + cq + 4 * j] = *(const float4*)(vsrc + 4 * j);
            }
        }
        __syncthreads();

        {
            const int c0 = tx * 4;
            float sv[4][4];
#pragma unroll
            for (int i = 0; i < 4; ++i)
#pragma unroll
                for (int j = 0; j < 4; ++j) sv[i][j] = 0.f;

#pragma unroll 4
            for (int kk = 0; kk < 128; ++kk) {
                float a[4], bv[4];
                *(float4*)a  = *(const float4*)&Qt[kk * 64 + r0];
                *(float4*)bv = *(const float4*)&Kt[kk * 64 + c0];
#pragma unroll
                for (int i = 0; i < 4; ++i)
#pragma unroll
                    for (int j = 0; j < 4; ++j) sv[i][j] += a[i] * bv[j];
            }
#pragma unroll
            for (int i = 0; i < 4; ++i) {
                const int qi = qt * BQ + r0 + i;
#pragma unroll
                for (int j = 0; j < 4; ++j) {
                    const int kj = kt * BKT + c0 + j;
                    float val = (kj <= qi) ? (sv[i][j] * KEY_SCALE + (float)(kj - qi) * hs)
                                           : -INFINITY;
                    Sst[(r0 + i) * SS_LD + c0 + j] = val;
                }
            }
        }
        __syncthreads();

        {
            const int row = tid >> 2;
            const int quarter = tid & 3;
            float* srow = &Sst[row * SS_LD];
            const int cbase = quarter * 16;
            float mx = -INFINITY;
#pragma unroll
            for (int c = 0; c < 16; ++c) mx = fmaxf(mx, srow[cbase + c]);
            mx = fmaxf(mx, __shfl_xor_sync(0xffffffffu, mx, 1));
            mx = fmaxf(mx, __shfl_xor_sync(0xffffffffu, mx, 2));
            const float m_old = m_s[row];
            const float m_new = fmaxf(m_old, mx);
            float psum = 0.f;
#pragma unroll
            for (int c = 0; c < 16; ++c) {
                const float p = __expf(srow[cbase + c] - m_new);
                srow[cbase + c] = p;
                psum += p;
            }
            psum += __shfl_xor_sync(0xffffffffu, psum, 1);
            psum += __shfl_xor_sync(0xffffffffu, psum, 2);
            if (quarter == 0) {
                const float alpha = __expf(m_old - m_new);
                a_s[row] = alpha;
                l_s[row] = l_s[row] * alpha + psum;
                m_s[row] = m_new;
            }
        }
        __syncthreads();

        {
            const int c0 = tx * 8;
            float al[4];
#pragma unroll
            for (int i = 0; i < 4; ++i) al[i] = a_s[r0 + i];
#pragma unroll
            for (int i = 0; i < 4; ++i)
#pragma unroll
                for (int j = 0; j < 8; ++j) acc[i][j] *= al[i];

#pragma unroll 4
            for (int kk = 0; kk < 64; ++kk) {
                float p[4];
#pragma unroll
                for (int i = 0; i < 4; ++i) p[i] = Sst[(r0 + i) * SS_LD + kk];
                float vv[8];
                *(float4*)&vv[0] = *(const float4*)&Vs[kk * 128 + c0];
                *(float4*)&vv[4] = *(const float4*)&Vs[kk * 128 + c0 + 4];
#pragma unroll
                for (int i = 0; i < 4; ++i)
#pragma unroll
                    for (int j = 0; j < 8; ++j) acc[i][j] += p[i] * vv[j];
            }
        }
    }

    {
        const int c0 = tx * 8;
#pragma unroll
        for (int i = 0; i < 4; ++i) {
            const int qg = qt * BQ + r0 + i;
            const float inv = 1.f / l_s[r0 + i];
            const float gt = gate[((size_t)b * SS + qg) * HH + h];
            const float sc = inv * gt;
            float4 o0, o1;
            o0.x = acc[i][0] * sc; o0.y = acc[i][1] * sc;
            o0.z = acc[i][2] * sc; o0.w = acc[i][3] * sc;
            o1.x = acc[i][4] * sc; o1.y = acc[i][5] * sc;
            o1.z = acc[i][6] * sc; o1.w = acc[i][7] * sc;
            float* dst = o + (((size_t)b * SS + qg) * HH + h) * DK + c0;
            *(float4*)dst = o0;
            *(float4*)(dst + 4) = o1;
        }
    }
}

// ==================== launcher ====================
extern "C" void kernel_launch(void* const* d_in, const int* in_sizes, int n_in,
                              void* d_out, int out_size) {
    const float* states     = (const float*)d_in[0];
    // d_in[1] = bias_mask (unused: computed analytically, exact match)
    const float* head_scale = (const float*)d_in[2];
    const float* Wq = (const float*)d_in[3];
    const float* bq = (const float*)d_in[4];
    const float* Wk = (const float*)d_in[5];
    const float* bk = (const float*)d_in[6];
    const float* Wv = (const float*)d_in[7];
    const float* bv = (const float*)d_in[8];
    const float* Wg = (const float*)d_in[9];
    const float* bg = (const float*)d_in[10];
    const float* Wo = (const float*)d_in[11];
    const float* bo = (const float*)d_in[12];

    float *qb, *kb, *vb, *gb, *ob;
    cudaGetSymbolAddress((void**)&qb, g_q);
    cudaGetSymbolAddress((void**)&kb, g_k);
    cudaGetSymbolAddress((void**)&vb, g_v);
    cudaGetSymbolAddress((void**)&gb, g_gate);
    cudaGetSymbolAddress((void**)&ob, g_o);

    cudaFuncSetAttribute(attn_kernel, cudaFuncAttributeMaxDynamicSharedMemorySize,
                         ATTN_SMEM_BYTES);

    dim3 gemm_grid(DD / TBN, MM / TBM);   // (16, 32)
    gemm_tf32<<<gemm_grid, 256>>>(states, Wq, bq, qb, 1);
    gemm_tf32<<<gemm_grid, 256>>>(states, Wk, bk, kb, 1);
    gemm_tf32<<<gemm_grid, 256>>>(states, Wv, bv, vb, 1);
    gate_kernel<<<MM, 128>>>(states, Wg, bg, gb);

    dim3 attn_grid(SS / BQ, HH, BB);      // (32, 16, 2)
    attn_kernel<<<attn_grid, 256, ATTN_SMEM_BYTES>>>(qb, kb, vb, gb, ob, head_scale);

    gemm_tf32<<<gemm_grid, 256>>>(ob, Wo, bo, (float*)d_out, 0);
}

// round 3
// speedup vs baseline: 3.4547x; 1.9438x over previous
#include <cuda_runtime.h>
#include <cuda_bf16.h>
#include <math.h>
#include <stdint.h>

// Problem constants
#define BB 2
#define SS 2048
#define DD 2048
#define HH 16
#define DK 128
#define MM (BB*SS)          // 4096
#define KEY_SCALE 0.08838834764831843f  // 1/sqrt(128)

// -------------------- scratch (device globals; no allocations) --------------------
__device__ float g_q[(size_t)BB*HH*SS*DK];   // [b,h,s,dk]
__device__ float g_k[(size_t)BB*HH*SS*DK];
__device__ float g_v[(size_t)BB*HH*SS*DK];
__device__ float g_gate[(size_t)BB*SS*HH];   // [b,s,h]
__device__ float g_o[(size_t)BB*SS*DD];      // [b,s,h*dk]

__device__ __forceinline__ uint32_t tf32u(float x) {
    uint32_t u;
    asm("cvt.rna.tf32.f32 %0, %1;" : "=r"(u) : "f"(x));
    return u;
}
__device__ __forceinline__ float tf32f(float x) { return __uint_as_float(tf32u(x)); }

__device__ __forceinline__ void mma_tf32(float* d, const uint32_t* a, const uint32_t* b) {
    asm volatile(
        "mma.sync.aligned.m16n8k8.row.col.f32.tf32.tf32.f32 "
        "{%0,%1,%2,%3}, {%4,%5,%6,%7}, {%8,%9}, {%0,%1,%2,%3};"
        : "+f"(d[0]), "+f"(d[1]), "+f"(d[2]), "+f"(d[3])
        : "r"(a[0]), "r"(a[1]), "r"(a[2]), "r"(a[3]), "r"(b[0]), "r"(b[1]));
}

// ==================== TF32 tensor-core GEMM ====================
// C[M,N] = X[M,K] * W[N,K]^T + bias      (K = DD = 2048)
#define TBM 128
#define TBN 128
#define TBK 16
#define TLD 20
#define KTILES (DD / TBK)

__global__ __launch_bounds__(256) void gemm_tf32(const float* __restrict__ X,
                                                 const float* __restrict__ W,
                                                 const float* __restrict__ bias,
                                                 float* __restrict__ out,
                                                 int mode) {
    __shared__ float As[3][TBM * TLD];
    __shared__ float Bs[3][TBN * TLD];

    const int tid  = threadIdx.x;
    const int lane = tid & 31;
    const int warp = tid >> 5;
    const int gid  = lane >> 2;
    const int ctid = lane & 3;
    const int wr   = warp >> 2;
    const int wc   = warp & 3;
    const int mw   = wr * 64;
    const int nw   = wc * 32;

    const int m0 = blockIdx.y * TBM;
    const int n0 = blockIdx.x * TBN;

    const int lrow = tid >> 2;
    const int lcol = (tid & 3) * 4;

    const float* Xp0 = X + (size_t)(m0 + lrow) * DD + lcol;
    const float* Xp1 = X + (size_t)(m0 + lrow + 64) * DD + lcol;
    const float* Wp0 = W + (size_t)(n0 + lrow) * DD + lcol;
    const float* Wp1 = W + (size_t)(n0 + lrow + 64) * DD + lcol;

    float4 sx0, sx1, sw0, sw1;

#define LDG_TILE(t) do {                                        \
        const size_t off = (size_t)(t) * TBK;                   \
        sx0 = *(const float4*)(Xp0 + off);                      \
        sx1 = *(const float4*)(Xp1 + off);                      \
        sw0 = *(const float4*)(Wp0 + off);                      \
        sw1 = *(const float4*)(Wp1 + off);                      \
    } while (0)

#define STS_TILE(buf) do {                                      \
        float* ap0 = &As[buf][lrow * TLD + lcol];               \
        ap0[0] = tf32f(sx0.x); ap0[1] = tf32f(sx0.y);           \
        ap0[2] = tf32f(sx0.z); ap0[3] = tf32f(sx0.w);           \
        float* ap1 = &As[buf][(lrow + 64) * TLD + lcol];        \
        ap1[0] = tf32f(sx1.x); ap1[1] = tf32f(sx1.y);           \
        ap1[2] = tf32f(sx1.z); ap1[3] = tf32f(sx1.w);           \
        float* bp0 = &Bs[buf][lrow * TLD + lcol];               \
        bp0[0] = tf32f(sw0.x); bp0[1] = tf32f(sw0.y);           \
        bp0[2] = tf32f(sw0.z); bp0[3] = tf32f(sw0.w);           \
        float* bp1 = &Bs[buf][(lrow + 64) * TLD + lcol];        \
        bp1[0] = tf32f(sw1.x); bp1[1] = tf32f(sw1.y);           \
        bp1[2] = tf32f(sw1.z); bp1[3] = tf32f(sw1.w);           \
    } while (0)

    float acc[4][4][4];
#pragma unroll
    for (int i = 0; i < 4; ++i)
#pragma unroll
        for (int j = 0; j < 4; ++j)
#pragma unroll
            for (int r = 0; r < 4; ++r) acc[i][j][r] = 0.f;

    LDG_TILE(0);
    STS_TILE(0);
    LDG_TILE(1);

    for (int t = 0; t < KTILES; ++t) {
        const int bufc = t % 3;
        if (t + 1 < KTILES) STS_TILE((t + 1) % 3);
        if (t + 2 < KTILES) LDG_TILE(t + 2);
        __syncthreads();

        const float* Ab = As[bufc];
        const float* Bb = Bs[bufc];

#pragma unroll
        for (int ks = 0; ks < 2; ++ks) {
            const int kk = ks * 8;
            uint32_t a[4][4], b[4][2];
#pragma unroll
            for (int mt = 0; mt < 4; ++mt) {
                const int r = mw + mt * 16 + gid;
                a[mt][0] = __float_as_uint(Ab[(r)     * TLD + kk + ctid]);
                a[mt][1] = __float_as_uint(Ab[(r + 8) * TLD + kk + ctid]);
                a[mt][2] = __float_as_uint(Ab[(r)     * TLD + kk + ctid + 4]);
                a[mt][3] = __float_as_uint(Ab[(r + 8) * TLD + kk + ctid + 4]);
            }
#pragma unroll
            for (int nt = 0; nt < 4; ++nt) {
                const int c = nw + nt * 8 + gid;
                b[nt][0] = __float_as_uint(Bb[c * TLD + kk + ctid]);
                b[nt][1] = __float_as_uint(Bb[c * TLD + kk + ctid + 4]);
            }
#pragma unroll
            for (int mt = 0; mt < 4; ++mt)
#pragma unroll
                for (int nt = 0; nt < 4; ++nt)
                    mma_tf32(acc[mt][nt], a[mt], b[nt]);
        }
    }

#pragma unroll
    for (int mt = 0; mt < 4; ++mt) {
#pragma unroll
        for (int nt = 0; nt < 4; ++nt) {
            const int row0 = m0 + mw + mt * 16 + gid;
            const int col  = n0 + nw + nt * 8 + ctid * 2;
            const float b0 = bias[col], b1 = bias[col + 1];
            float2 v0 = make_float2(acc[mt][nt][0] + b0, acc[mt][nt][1] + b1);
            float2 v1 = make_float2(acc[mt][nt][2] + b0, acc[mt][nt][3] + b1);
            if (mode == 0) {
                *(float2*)&out[(size_t)row0 * DD + col] = v0;
                *(float2*)&out[(size_t)(row0 + 8) * DD + col] = v1;
            } else {
                const int h_ = col >> 7, dk_ = col & (DK - 1);
                const int b0_ = row0 >> 11, s0_ = row0 & (SS - 1);
                const int s1_ = (row0 + 8) & (SS - 1);
                *(float2*)&out[(((size_t)(b0_ * HH + h_) * SS) + s0_) * DK + dk_] = v0;
                *(float2*)&out[(((size_t)(b0_ * HH + h_) * SS) + s1_) * DK + dk_] = v1;
            }
        }
    }
#undef LDG_TILE
#undef STS_TILE
}

// ==================== gate ====================
__global__ __launch_bounds__(128) void gate_kernel(const float* __restrict__ X,
                                                   const float* __restrict__ Wg,
                                                   const float* __restrict__ bg,
                                                   float* __restrict__ gate) {
    __shared__ float xs[DD];
    const int m = blockIdx.x;
    for (int i = threadIdx.x * 4; i < DD; i += 128 * 4)
        *(float4*)&xs[i] = *(const float4*)&X[(size_t)m * DD + i];
    __syncthreads();

    const int w = threadIdx.x >> 5, lane = threadIdx.x & 31;
    for (int h = w; h < HH; h += 4) {
        const float* wg = &Wg[(size_t)h * DD];
        float sum = 0.f;
        for (int k = lane; k < DD; k += 32) sum += xs[k] * wg[k];
#pragma unroll
        for (int off = 16; off; off >>= 1) sum += __shfl_xor_sync(0xffffffffu, sum, off);
        if (lane == 0) {
            const float z = sum + bg[h];
            gate[(size_t)m * HH + h] = 1.f / (1.f + __expf(-z));
        }
    }
}

// ==================== flash attention (tf32 tensor cores) ====================
// BQ=128 rows/block (8 warps x 16), BK=64 keys/tile.
#define AQ 128
#define AK 64
#define KS_LD 132      // K smem row stride (128 + 4)
#define VT_LD 68       // V^T smem row stride (64 + 4)
#define ATTN_SMEM_BYTES ((AK * KS_LD + DK * VT_LD) * 4)

__global__ __launch_bounds__(256, 1) void attn_mma(const float* __restrict__ q,
                                                   const float* __restrict__ k,
                                                   const float* __restrict__ v,
                                                   const float* __restrict__ gate,
                                                   float* __restrict__ o,
                                                   const float* __restrict__ head_scale) {
    extern __shared__ float sm[];
    float* Ks = sm;                    // [AK][KS_LD]   K row-major (tf32)
    float* Vt = sm + AK * KS_LD;       // [DK][VT_LD]   V transposed (tf32)

    const int qb   = gridDim.x - 1 - blockIdx.x;   // reverse: heavy blocks first
    const int h    = blockIdx.y;
    const int b    = blockIdx.z;
    const int tid  = threadIdx.x;
    const int lane = tid & 31;
    const int warp = tid >> 5;
    const int gid  = lane >> 2;
    const int ctid = lane & 3;
    const float hs = head_scale[h];
    const size_t bh = ((size_t)b * HH + h) * SS;

    const int rowA = qb * AQ + warp * 16 + gid;
    const int rowB = rowA + 8;

    // Q fragments (registers, tf32): qa[kc][4] covering dk = 8*kc + {ctid, ctid+4}
    uint32_t qa[16][4];
    {
        const float* qA = q + (bh + rowA) * DK;
        const float* qB = q + (bh + rowB) * DK;
#pragma unroll
        for (int kc = 0; kc < 16; ++kc) {
            qa[kc][0] = tf32u(qA[8 * kc + ctid]);
            qa[kc][1] = tf32u(qB[8 * kc + ctid]);
            qa[kc][2] = tf32u(qA[8 * kc + ctid + 4]);
            qa[kc][3] = tf32u(qB[8 * kc + ctid + 4]);
        }
    }

    float oacc[16][4];
#pragma unroll
    for (int nt = 0; nt < 16; ++nt)
#pragma unroll
        for (int r = 0; r < 4; ++r) oacc[nt][r] = 0.f;

    float mA = -INFINITY, mB = -INFINITY, lA = 0.f, lB = 0.f;

    const int ktmax = 2 * qb + 1;
    for (int kt = 0; kt <= ktmax; ++kt) {
        __syncthreads();   // previous tile fully consumed

        // ---- load K tile (row-major, warp per row: coalesced) ----
        {
            int s = tid;
#pragma unroll
            for (int i = 0; i < 8; ++i, s += 256) {
                const int r = s >> 5, c4 = (s & 31) * 4;
                float4 xv = *(const float4*)&k[(bh + (size_t)kt * AK + r) * DK + c4];
                float4 tv = make_float4(tf32f(xv.x), tf32f(xv.y), tf32f(xv.z), tf32f(xv.w));
                *(float4*)&Ks[r * KS_LD + c4] = tv;
            }
        }
        // ---- load V tile transposed (quad-segmented load, 2-way-conflict STS) ----
        {
#pragma unroll
            for (int i = 0; i < 8; ++i) {
                const int r = i * 8 + (lane >> 2);
                const int c = warp * 16 + (lane & 3) * 4;
                float4 xv = *(const float4*)&v[(bh + (size_t)kt * AK + r) * DK + c];
                Vt[(c + 0) * VT_LD + r] = tf32f(xv.x);
                Vt[(c + 1) * VT_LD + r] = tf32f(xv.y);
                Vt[(c + 2) * VT_LD + r] = tf32f(xv.z);
                Vt[(c + 3) * VT_LD + r] = tf32f(xv.w);
            }
        }
        __syncthreads();

        // ---- S = Q K^T  (8 n-tiles of 8 keys) ----
        float sacc[8][4];
#pragma unroll
        for (int nt = 0; nt < 8; ++nt)
#pragma unroll
            for (int r = 0; r < 4; ++r) sacc[nt][r] = 0.f;

#pragma unroll
        for (int kc = 0; kc < 16; ++kc) {
#pragma unroll
            for (int nt = 0; nt < 8; ++nt) {
                uint32_t bfr[2];
                const float* kp = &Ks[(8 * nt + gid) * KS_LD + 8 * kc + ctid];
                bfr[0] = __float_as_uint(kp[0]);
                bfr[1] = __float_as_uint(kp[4]);
                mma_tf32(sacc[nt], qa[kc], bfr);
            }
        }

        // ---- scale + ALiBi + causal mask ----
        const int kbase = kt * AK;
#pragma unroll
        for (int nt = 0; nt < 8; ++nt) {
            const int c0 = kbase + 8 * nt + 2 * ctid;
            const int c1 = c0 + 1;
            sacc[nt][0] = (c0 <= rowA) ? sacc[nt][0] * KEY_SCALE + (float)(c0 - rowA) * hs : -INFINITY;
            sacc[nt][1] = (c1 <= rowA) ? sacc[nt][1] * KEY_SCALE + (float)(c1 - rowA) * hs : -INFINITY;
            sacc[nt][2] = (c0 <= rowB) ? sacc[nt][2] * KEY_SCALE + (float)(c0 - rowB) * hs : -INFINITY;
            sacc[nt][3] = (c1 <= rowB) ? sacc[nt][3] * KEY_SCALE + (float)(c1 - rowB) * hs : -INFINITY;
        }

        // ---- online softmax (row stats across quad) ----
        float mxA = -INFINITY, mxB = -INFINITY;
#pragma unroll
        for (int nt = 0; nt < 8; ++nt) {
            mxA = fmaxf(mxA, fmaxf(sacc[nt][0], sacc[nt][1]));
            mxB = fmaxf(mxB, fmaxf(sacc[nt][2], sacc[nt][3]));
        }
        mxA = fmaxf(mxA, __shfl_xor_sync(0xffffffffu, mxA, 1));
        mxA = fmaxf(mxA, __shfl_xor_sync(0xffffffffu, mxA, 2));
        mxB = fmaxf(mxB, __shfl_xor_sync(0xffffffffu, mxB, 1));
        mxB = fmaxf(mxB, __shfl_xor_sync(0xffffffffu, mxB, 2));

        const float mA_new = fmaxf(mA, mxA);
        const float mB_new = fmaxf(mB, mxB);
        const float alphaA = __expf(mA - mA_new);
        const float alphaB = __expf(mB - mB_new);
        mA = mA_new; mB = mB_new;

        float rsA = 0.f, rsB = 0.f;
        uint32_t pfrag[8][4];
        const int qsrc0 = (lane & ~3) + (ctid >> 1);
        const int qsrc2 = qsrc0 + 2;
        const bool oddc = (ctid & 1);
#pragma unroll
        for (int nt = 0; nt < 8; ++nt) {
            float p0 = __expf(sacc[nt][0] - mA_new);
            float p1 = __expf(sacc[nt][1] - mA_new);
            float p2 = __expf(sacc[nt][2] - mB_new);
            float p3 = __expf(sacc[nt][3] - mB_new);
            rsA += p0 + p1;
            rsB += p2 + p3;
            uint32_t t0 = tf32u(p0), t1 = tf32u(p1), t2 = tf32u(p2), t3 = tf32u(p3);
            // quad shuffle: C-layout (cols 2c,2c+1) -> A-frag layout (cols c, c+4)
            uint32_t v00 = __shfl_sync(0xffffffffu, t0, qsrc0);
            uint32_t v01 = __shfl_sync(0xffffffffu, t1, qsrc0);
            uint32_t v20 = __shfl_sync(0xffffffffu, t0, qsrc2);
            uint32_t v21 = __shfl_sync(0xffffffffu, t1, qsrc2);
            uint32_t w00 = __shfl_sync(0xffffffffu, t2, qsrc0);
            uint32_t w01 = __shfl_sync(0xffffffffu, t3, qsrc0);
            uint32_t w20 = __shfl_sync(0xffffffffu, t2, qsrc2);
            uint32_t w21 = __shfl_sync(0xffffffffu, t3, qsrc2);
            pfrag[nt][0] = oddc ? v01 : v00;   // rowA, col ctid
            pfrag[nt][1] = oddc ? w01 : w00;   // rowB, col ctid
            pfrag[nt][2] = oddc ? v21 : v20;   // rowA, col ctid+4
            pfrag[nt][3] = oddc ? w21 : w20;   // rowB, col ctid+4
        }
        rsA += __shfl_xor_sync(0xffffffffu, rsA, 1);
        rsA += __shfl_xor_sync(0xffffffffu, rsA, 2);
        rsB += __shfl_xor_sync(0xffffffffu, rsB, 1);
        rsB += __shfl_xor_sync(0xffffffffu, rsB, 2);
        lA = lA * alphaA + rsA;
        lB = lB * alphaB + rsB;

        // ---- rescale O, accumulate P V ----
#pragma unroll
        for (int nt = 0; nt < 16; ++nt) {
            oacc[nt][0] *= alphaA; oacc[nt][1] *= alphaA;
            oacc[nt][2] *= alphaB; oacc[nt][3] *= alphaB;
        }
#pragma unroll
        for (int kc = 0; kc < 8; ++kc) {
#pragma unroll
            for (int nt = 0; nt < 16; ++nt) {
                uint32_t bfr[2];
                const float* vp = &Vt[(8 * nt + gid) * VT_LD + 8 * kc + ctid];
                bfr[0] = __float_as_uint(vp[0]);
                bfr[1] = __float_as_uint(vp[4]);
                mma_tf32(oacc[nt], pfrag[kc], bfr);
            }
        }
    }

    // ---- epilogue: normalize, gate, store [b,s,h*dk] ----
    const float gA = gate[((size_t)b * SS + rowA) * HH + h] / lA;
    const float gB = gate[((size_t)b * SS + rowB) * HH + h] / lB;
#pragma unroll
    for (int nt = 0; nt < 16; ++nt) {
        const int col = h * DK + 8 * nt + 2 * ctid;
        float2 vA = make_float2(oacc[nt][0] * gA, oacc[nt][1] * gA);
        float2 vB = make_float2(oacc[nt][2] * gB, oacc[nt][3] * gB);
        *(float2*)&o[((size_t)b * SS + rowA) * DD + col] = vA;
        *(float2*)&o[((size_t)b * SS + rowB) * DD + col] = vB;
    }
}

// ==================== launcher ====================
extern "C" void kernel_launch(void* const* d_in, const int* in_sizes, int n_in,
                              void* d_out, int out_size) {
    const float* states     = (const float*)d_in[0];
    const float* head_scale = (const float*)d_in[2];
    const float* Wq = (const float*)d_in[3];
    const float* bq = (const float*)d_in[4];
    const float* Wk = (const float*)d_in[5];
    const float* bk = (const float*)d_in[6];
    const float* Wv = (const float*)d_in[7];
    const float* bv = (const float*)d_in[8];
    const float* Wg = (const float*)d_in[9];
    const float* bg = (const float*)d_in[10];
    const float* Wo = (const float*)d_in[11];
    const float* bo = (const float*)d_in[12];

    float *qb, *kb, *vb, *gb, *ob;
    cudaGetSymbolAddress((void**)&qb, g_q);
    cudaGetSymbolAddress((void**)&kb, g_k);
    cudaGetSymbolAddress((void**)&vb, g_v);
    cudaGetSymbolAddress((void**)&gb, g_gate);
    cudaGetSymbolAddress((void**)&ob, g_o);

    cudaFuncSetAttribute(attn_mma, cudaFuncAttributeMaxDynamicSharedMemorySize,
                         ATTN_SMEM_BYTES);

    dim3 gemm_grid(DD / TBN, MM / TBM);   // (16, 32)
    gemm_tf32<<<gemm_grid, 256>>>(states, Wq, bq, qb, 1);
    gemm_tf32<<<gemm_grid, 256>>>(states, Wk, bk, kb, 1);
    gemm_tf32<<<gemm_grid, 256>>>(states, Wv, bv, vb, 1);
    gate_kernel<<<MM, 128>>>(states, Wg, bg, gb);

    dim3 attn_grid(SS / AQ, HH, BB);      // (16, 16, 2)
    attn_mma<<<attn_grid, 256, ATTN_SMEM_BYTES>>>(qb, kb, vb, gb, ob, head_scale);

    gemm_tf32<<<gemm_grid, 256>>>(ob, Wo, bo, (float*)d_out, 0);
}